// round 4
// baseline (speedup 1.0000x reference)
#include <cuda_runtime.h>
#include <math.h>

#define C_    256
#define T_    8
#define H_    32
#define W_    32
#define L_    4
#define THW_  8192
#define NROWS 256              // L * 64 sample points
#define FEAT_OUT_ELEMS (C_*THW_*L_)   // 2097152

// ---- scratch (device globals; no allocation) ----
__device__ float g_glob[L_*C_];        // glob[l][c]
__device__ float g_s[NROWS];           // row -> softmax-sum scale
__device__ int   g_uq[NROWS*36];       // dedup indices (padded)
__device__ float g_uw[NROWS*36];       // dedup weights (padded, 0 fill)

__constant__ int c_tt[4] = {1,3,4,6};
__constant__ int c_hh[4] = {4,12,19,27};

__device__ __forceinline__ int flat_idx(int n){
    int it = n >> 4, ih = (n >> 2) & 3, iw = n & 3;
    return (c_tt[it]*H_ + c_hh[ih])*W_ + c_hh[iw];
}
__device__ __forceinline__ float sigmoidf_(float x){ return 1.0f/(1.0f+expf(-x)); }
__device__ __forceinline__ float invsigf_(float x){
    return logf(fmaxf(x,1e-5f)/fmaxf(1.0f-x,1e-5f));
}
__device__ __forceinline__ void cp_async16(void* smem_dst, const void* gmem_src){
    unsigned s = (unsigned)__cvta_generic_to_shared(smem_dst);
    asm volatile("cp.async.cg.shared.global [%0], [%1], 16;\n" :: "r"(s), "l"(gmem_src));
}
__device__ __forceinline__ void cp_commit(){ asm volatile("cp.async.commit_group;\n"); }
__device__ __forceinline__ void cp_wait0(){ asm volatile("cp.async.wait_group 0;\n"); }
__device__ __forceinline__ void cp_wait1(){ asm volatile("cp.async.wait_group 1;\n"); }

// ---- packed f32x2 helpers ----
typedef unsigned long long ull;
__device__ __forceinline__ ull fma2_(ull a, ull b, ull c){
    ull d; asm("fma.rn.f32x2 %0, %1, %2, %3;" : "=l"(d) : "l"(a), "l"(b), "l"(c)); return d;
}
__device__ __forceinline__ ull pack2_(float x, float y){
    ull r; asm("mov.b64 %0, {%1, %2};" : "=l"(r) : "f"(x), "f"(y)); return r;
}
__device__ __forceinline__ float2 unpack2_(ull v){
    float2 r; asm("mov.b64 {%0, %1}, %2;" : "=f"(r.x), "=f"(r.y) : "l"(v)); return r;
}

// ============================================================
// Kernel 1: glob[l][c] = mean over THW of features[0,c,:,:,:,l]
// ============================================================
__global__ void glob_kernel(const float* __restrict__ feats){
    int c = blockIdx.x;
    const float4* f4 = reinterpret_cast<const float4*>(feats + (size_t)c * (THW_*L_));
    float4 s = make_float4(0.f,0.f,0.f,0.f);
    for (int i = threadIdx.x; i < THW_; i += 256){
        float4 v = f4[i];
        s.x += v.x; s.y += v.y; s.z += v.z; s.w += v.w;
    }
    __shared__ float4 sm[256];
    sm[threadIdx.x] = s;
    __syncthreads();
    for (int o = 128; o > 0; o >>= 1){
        if (threadIdx.x < o){
            float4 a = sm[threadIdx.x], b = sm[threadIdx.x+o];
            sm[threadIdx.x] = make_float4(a.x+b.x, a.y+b.y, a.z+b.z, a.w+b.w);
        }
        __syncthreads();
    }
    if (threadIdx.x == 0){
        float4 t = sm[0];
        const float inv = 1.0f/8192.0f;
        g_glob[0*C_+c] = t.x*inv;
        g_glob[1*C_+c] = t.y*inv;
        g_glob[2*C_+c] = t.z*inv;
        g_glob[3*C_+c] = t.w*inv;
    }
}

// ============================================================
// Kernel 2: fused MLP + heads + corner dedup.
// 64 blocks x 512 threads, 4 rows/block.
// Thread = (col 0..255, khalf 0..1). K interleaved by parity.
// Dynamic smem (floats):
//   Xs  [768*4]  @0      H1 [1024] @3072   H2 [1024] @4096
//   HWn [768] @5120  HWl [1024] @5888  HWo [192] @6912  HWw [128] @7104
//   PART[1024] @7232
//   Wb  [2][16384] @8256
// total = 41024 floats = 164096 bytes
// ============================================================
#define KT 64
#define SM_XS   0
#define SM_H1   3072
#define SM_H2   4096
#define SM_WN   5120
#define SM_WL   5888
#define SM_WOF  6912
#define SM_WW   7104
#define SM_PART 7232
#define SM_WB   8256
#define MLP_SMEM_BYTES (41024*4)

__global__ void __launch_bounds__(512, 1)
mlp_kernel(const float* __restrict__ feats, const float* __restrict__ pos,
    const float* __restrict__ W1, const float* __restrict__ b1,
    const float* __restrict__ W2, const float* __restrict__ b2,
    const float* __restrict__ Wn, const float* __restrict__ bn,
    const float* __restrict__ Wl, const float* __restrict__ bl,
    const float* __restrict__ Woff, const float* __restrict__ boff,
    const float* __restrict__ Ww, const float* __restrict__ bw,
    float* __restrict__ out, int write_next)
{
    extern __shared__ float smem[];
    float* Xs  = smem + SM_XS;
    float* H1  = smem + SM_H1;
    float* H2  = smem + SM_H2;
    float* HWn = smem + SM_WN;
    float* HWl = smem + SM_WL;
    float* HWo = smem + SM_WOF;
    float* HWw = smem + SM_WW;
    float* PART= smem + SM_PART;
    float* Wb0 = smem + SM_WB;
    float* Wb1 = smem + SM_WB + KT*256;
    __shared__ float HD[4][28];
    __shared__ float SPx[4][4], SPy[4][4], SPz[4][4], SPw[4][4];
    __shared__ int   cq[4][36];
    __shared__ float cw[4][36];

    int tid  = threadIdx.x;
    int col  = tid & 255;
    int half = tid >> 8;
    int r0   = blockIdx.x * 4;
    int l    = r0 >> 6;

    // ---- prefetch W1 tile 0 (8 float4 per thread)
    const float4* W1v = reinterpret_cast<const float4*>(W1);
    {
        #pragma unroll
        for (int u = 0; u < 8; u++)
            cp_async16((float4*)Wb0 + tid + u*512, W1v + tid + u*512);
        cp_commit();
    }

    // ---- gather Xs[k*4+r] : [feat(256) | pos(256) | glob(256)]
    #pragma unroll
    for (int r = 0; r < 4; r++){
        int p = flat_idx((r0 + r) & 63);
        for (int k = tid; k < 768; k += 512){
            float v;
            if (k < 256)       v = feats[((size_t)k*THW_ + p)*L_ + l];
            else if (k < 512)  v = pos  [((size_t)(k-256)*THW_ + p)*L_ + l];
            else               v = g_glob[l*C_ + (k-512)];
            Xs[k*4 + r] = v;
        }
    }
    // ---- head weights to smem
    for (int k = tid; k < 768;  k += 512) HWn[k] = Wn[k];
    for (int k = tid; k < 1024; k += 512) HWl[k] = Wl[k];
    if (tid < 192) HWo[tid] = Woff[tid];
    else if (tid >= 256 && tid < 384) HWw[tid-256] = Ww[tid-256];
    __syncthreads();

    // ---- layer 1: K=768, 12 tiles of 64, parity-split across halves
    ull acc01, acc23;
    {
        float bias = b1[col];
        acc01 = half ? 0ULL : pack2_(bias, bias);
        acc23 = acc01;
        #pragma unroll 1
        for (int t = 0; t < 12; t++){
            float* Wcur = (t & 1) ? Wb1 : Wb0;
            float* Wnxt = (t & 1) ? Wb0 : Wb1;
            if (t + 1 < 12){
                const float4* src = W1v + (t+1)*4096;
                #pragma unroll
                for (int u = 0; u < 8; u++)
                    cp_async16((float4*)Wnxt + tid + u*512, src + tid + u*512);
                cp_commit();
                cp_wait1();
            } else {
                cp_wait0();
            }
            __syncthreads();
            #pragma unroll 8
            for (int ki = 0; ki < 32; ki++){
                int k = ki*2 + half;
                float w = Wcur[k*256 + col];
                ull w2 = pack2_(w, w);
                const float* xb = Xs + (t*KT + k)*4;
                ull x01 = *(const ull*)(xb);
                ull x23 = *(const ull*)(xb + 2);
                acc01 = fma2_(x01, w2, acc01);
                acc23 = fma2_(x23, w2, acc23);
            }
            __syncthreads();
        }
    }
    // prefetch W2 tile 0 into Wb0 (free now)
    const float4* W2v = reinterpret_cast<const float4*>(W2);
    {
        #pragma unroll
        for (int u = 0; u < 8; u++)
            cp_async16((float4*)Wb0 + tid + u*512, W2v + tid + u*512);
        cp_commit();
    }
    // combine halves, relu, store H1[k*4+r]
    if (half){
        float2 a = unpack2_(acc01), b = unpack2_(acc23);
        *(float4*)(PART + col*4) = make_float4(a.x, a.y, b.x, b.y);
    }
    __syncthreads();
    if (!half){
        float4 pp = *(float4*)(PART + col*4);
        float2 a = unpack2_(acc01), b = unpack2_(acc23);
        float4 h = make_float4(fmaxf(a.x+pp.x,0.f), fmaxf(a.y+pp.y,0.f),
                               fmaxf(b.x+pp.z,0.f), fmaxf(b.y+pp.w,0.f));
        *(float4*)(H1 + col*4) = h;
    }
    __syncthreads();

    // ---- layer 2: K=256, 4 tiles of 64
    {
        float bias = b2[col];
        acc01 = half ? 0ULL : pack2_(bias, bias);
        acc23 = acc01;
        #pragma unroll 1
        for (int t = 0; t < 4; t++){
            float* Wcur = (t & 1) ? Wb1 : Wb0;
            float* Wnxt = (t & 1) ? Wb0 : Wb1;
            if (t + 1 < 4){
                const float4* src = W2v + (t+1)*4096;
                #pragma unroll
                for (int u = 0; u < 8; u++)
                    cp_async16((float4*)Wnxt + tid + u*512, src + tid + u*512);
                cp_commit();
                cp_wait1();
            } else {
                cp_wait0();
            }
            __syncthreads();
            #pragma unroll 8
            for (int ki = 0; ki < 32; ki++){
                int k = ki*2 + half;
                float w = Wcur[k*256 + col];
                ull w2 = pack2_(w, w);
                const float* xb = H1 + (t*KT + k)*4;
                ull x01 = *(const ull*)(xb);
                ull x23 = *(const ull*)(xb + 2);
                acc01 = fma2_(x01, w2, acc01);
                acc23 = fma2_(x23, w2, acc23);
            }
            __syncthreads();
        }
    }
    if (half){
        float2 a = unpack2_(acc01), b = unpack2_(acc23);
        *(float4*)(PART + col*4) = make_float4(a.x, a.y, b.x, b.y);
    }
    __syncthreads();
    if (!half){
        float4 pp = *(float4*)(PART + col*4);
        float2 a = unpack2_(acc01), b = unpack2_(acc23);
        float4 h = make_float4(fmaxf(a.x+pp.x,0.f), fmaxf(a.y+pp.y,0.f),
                               fmaxf(b.x+pp.z,0.f), fmaxf(b.y+pp.w,0.f));
        *(float4*)(H2 + col*4) = h;
    }
    __syncthreads();

    // ---- heads: 128 threads per row (r = tid>>7), H2[k*4+r]
    int r = tid >> 7;
    int t = tid & 127;
    if (t < 3){                               // nxt
        float s = bn[t];
        #pragma unroll 8
        for (int k = 0; k < 256; k++) s = fmaf(H2[k*4 + r], HWn[k*3 + t], s);
        HD[r][t] = s;
    } else if (t >= 4 && t < 8){              // wl logits
        int jl = t - 4;
        float s = bl[jl];
        #pragma unroll 8
        for (int k = 0; k < 256; k++) s = fmaf(H2[k*4 + r], HWl[k*4 + jl], s);
        HD[r][t] = s;
    } else if (t >= 8 && t < 20){             // offsets
        int u = t - 8;
        int no = u / 3, jo = u - no*3;
        float s = boff[jo];
        #pragma unroll 8
        for (int dd = 0; dd < 64; dd++) s = fmaf(H2[(no*64+dd)*4 + r], HWo[dd*3 + jo], s);
        HD[r][8+u] = s;
    } else if (t >= 20 && t < 28){            // w_o logits
        int u = t - 20;
        int no = u >> 1, comp = u & 1;
        float s = bw[comp];
        #pragma unroll 8
        for (int dd = 0; dd < 64; dd++) s = fmaf(H2[(no*64+dd)*4 + r], HWw[dd*2 + comp], s);
        HD[r][20+u] = s;
    }
    __syncthreads();

    if (t == 0){
        int rr = r0 + r;
        int p  = flat_idx(rr & 63);
        int tq = p >> 10, hq = (p >> 5) & 31, wq = p & 31;
        float tn = (float)tq * (1.0f/7.0f);
        float hn = (float)hq * (1.0f/31.0f);
        float wn = (float)wq * (1.0f/31.0f);
        float ivt = invsigf_(tn), ivh = invsigf_(hn), ivw = invsigf_(wn);

        float z0 = HD[r][4], z1 = HD[r][5], z2 = HD[r][6], z3 = HD[r][7];
        float m  = fmaxf(fmaxf(z0,z1), fmaxf(z2,z3));
        float e0 = expf(z0-m), e1 = expf(z1-m), e2 = expf(z2-m), e3 = expf(z3-m);
        float S  = e0+e1+e2+e3;
        g_s[rr]  = e0/S + e1/S + e2/S + e3/S;

        #pragma unroll
        for (int no = 0; no < 4; no++){
            float o0 = HD[r][8+no*3+0], o1 = HD[r][8+no*3+1], o2 = HD[r][8+no*3+2];
            float st = sigmoidf_(ivt + o0)*2.0f - 1.0f;
            float sh = sigmoidf_(ivh + o1)*2.0f - 1.0f;
            float sw = sigmoidf_(ivw + o2)*2.0f - 1.0f;
            SPx[r][no] = ((st + 1.0f)*32.0f - 1.0f)*0.5f;
            SPy[r][no] = ((sh + 1.0f)*32.0f - 1.0f)*0.5f;
            SPz[r][no] = ((sw + 1.0f)*8.0f  - 1.0f)*0.5f;
            float za = HD[r][20+no*2], zb = HD[r][21+no*2];
            SPw[r][no] = 1.0f/(1.0f + expf(za - zb));
        }

        if (write_next){
            float d0 = sigmoidf_(ivt + HD[r][0]) * 7.0f;
            float d1 = sigmoidf_(ivh + HD[r][1]) * 31.0f;
            float d2 = sigmoidf_(ivw + HD[r][2]) * 31.0f;
            int ni = 1024*(int)rintf(d0) + 32*(int)rintf(d1) + (int)rintf(d2);
            out[FEAT_OUT_ELEMS + rr] = (float)ni;
        }
    }
    __syncthreads();

    // ---- corner dedup: warp w handles row w (tid < 128)
    if (tid < 128){
        const unsigned full = 0xffffffffu;
        int rw   = tid >> 5;
        int lane = tid & 31;
        int rr   = r0 + rw;
        int p    = flat_idx(rr & 63);
        int no = lane >> 3, j = lane & 7;
        float ix = SPx[rw][no], iy = SPy[rw][no], iz = SPz[rw][no];
        float wo = SPw[rw][no];
        float x0f = floorf(ix), y0f = floorf(iy), z0f = floorf(iz);
        int dx = j & 1, dy = (j >> 1) & 1, dz = j >> 2;
        int xi = (int)x0f + dx, yi = (int)y0f + dy, zi = (int)z0f + dz;
        float fx = ix - x0f, fy = iy - y0f, fz = iz - z0f;
        float w = (dx ? fx : 1.0f-fx) * (dy ? fy : 1.0f-fy) * (dz ? fz : 1.0f-fz) * wo;
        bool valid = (xi >= 0) & (xi < W_) & (yi >= 0) & (yi < H_) & (zi >= 0) & (zi < T_);
        if (!valid) w = 0.0f;
        int q = (min(max(zi,0),T_-1)*H_ + min(max(yi,0),H_-1))*W_ + min(max(xi,0),W_-1);

        unsigned mask = __match_any_sync(full, q);
        float wsum = 0.0f;
        #pragma unroll
        for (int s2 = 0; s2 < 32; s2++){
            float wv = __shfl_sync(full, w, s2);
            int   qv = __shfl_sync(full, q, s2);
            if (qv == q) wsum += wv;
        }
        int leader = __ffs(mask) - 1;
        bool is_leader = (lane == leader);
        unsigned bal = __ballot_sync(full, is_leader);
        int pos = __popc(bal & ((1u << lane) - 1u));

        if (lane < 32){
            cq[rw][lane] = 0; cw[rw][lane] = 0.0f;
            if (lane < 4){ cq[rw][32+lane] = 0; cw[rw][32+lane] = 0.0f; }
        }
        __syncwarp();
        if (is_leader){ cq[rw][pos] = q; cw[rw][pos] = wsum; }
        __syncwarp();
        if (lane == 0){
            int nq = __popc(bal);
            bool found = false;
            for (int j2 = 0; j2 < nq; j2++){
                if (cq[rw][j2] == p){ cw[rw][j2] += 1.0f; found = true; break; }
            }
            if (!found){ cq[rw][nq] = p; cw[rw][nq] = 1.0f; }
        }
        __syncwarp();
        for (int i2 = lane; i2 < 36; i2 += 32){
            g_uq[rr*36 + i2] = cq[rw][i2];
            g_uw[rr*36 + i2] = cw[rw][i2];
        }
    }
}

// ============================================================
// Kernel 3: fill with beta[c], skipping the 64 sampled positions
// ============================================================
__global__ void fill_kernel(const float* __restrict__ beta, float4* __restrict__ out){
    int i = blockIdx.x * blockDim.x + threadIdx.x;      // 524288 float4s
    float b = __ldg(&beta[i >> 13]);
    int p = i & 8191;
    int t3 = p >> 10, h3 = (p >> 5) & 31, w3 = p & 31;
    const unsigned tm = 0x5Au;                           // bits 1,3,4,6
    const unsigned hm = (1u<<4)|(1u<<12)|(1u<<19)|(1u<<27);
    bool samp = ((tm >> t3) & 1u) && ((hm >> h3) & 1u) && ((hm >> w3) & 1u);
    if (!samp) out[i] = make_float4(b, b, b, b);
}

// ============================================================
// Kernel 4: 256 blocks x 512 threads. Table-driven gather + shuffle LN.
// ============================================================
__global__ void __launch_bounds__(512, 2)
sample_ln_kernel(const float* __restrict__ feats,
                 const float* __restrict__ gamma,
                 const float* __restrict__ beta,
                 float* __restrict__ out)
{
    int b  = blockIdx.x;           // row = l*64 + n
    int l  = b >> 6;
    int p  = flat_idx(b & 63);
    int tid = threadIdx.x;

    __shared__ int    uq[36];
    __shared__ float  uw[36];
    __shared__ float  partial[256];
    __shared__ float2 sred[16];
    __shared__ float  s_scale, s_mu, s_rstd;

    if (tid < 36){ uq[tid] = g_uq[b*36 + tid]; uw[tid] = g_uw[b*36 + tid]; }
    if (tid == 64) s_scale = g_s[b];
    __syncthreads();

    int col  = tid & 255;
    int half = tid >> 8;
    const float* fb = feats + (size_t)col*(THW_*L_) + l;

    float a0 = 0.0f, a1 = 0.0f;
    #pragma unroll
    for (int j = 0; j < 18; j += 2){
        a0 = fmaf(uw[half + 2*j],     __ldg(fb + (size_t)uq[half + 2*j]*L_),     a0);
        a1 = fmaf(uw[half + 2*(j+1)], __ldg(fb + (size_t)uq[half + 2*(j+1)]*L_), a1);
    }
    float mine = a0 + a1;
    if (half) partial[col] = mine;
    __syncthreads();

    float v = 0.0f;
    if (!half) v = (mine + partial[col]) * s_scale;

    // shuffle-based fused mean/var reduction
    const unsigned full = 0xffffffffu;
    float sx = v, sy = v*v;
    #pragma unroll
    for (int o = 16; o > 0; o >>= 1){
        sx += __shfl_xor_sync(full, sx, o);
        sy += __shfl_xor_sync(full, sy, o);
    }
    int lane = tid & 31, wrp = tid >> 5;
    if (lane == 0) sred[wrp] = make_float2(sx, sy);
    __syncthreads();
    if (tid < 16){
        float2 a = sred[tid];
        #pragma unroll
        for (int o = 8; o > 0; o >>= 1){
            a.x += __shfl_xor_sync(0xffffu, a.x, o);
            a.y += __shfl_xor_sync(0xffffu, a.y, o);
        }
        if (tid == 0){
            float mu  = a.x * (1.0f/256.0f);
            float var = a.y * (1.0f/256.0f) - mu*mu;
            s_mu = mu;
            s_rstd = rsqrtf(var + 1e-5f);
        }
    }
    __syncthreads();

    if (!half){
        float o = (v - s_mu) * s_rstd * gamma[col] + beta[col];
        out[((size_t)col*THW_ + p)*L_ + l] = o;
    }
}

// ============================================================
extern "C" void kernel_launch(void* const* d_in, const int* in_sizes, int n_in,
                              void* d_out, int out_size)
{
    const float* feats = (const float*)d_in[0];
    const float* pos   = (const float*)d_in[1];
    const float* W1    = (const float*)d_in[2];
    const float* b1    = (const float*)d_in[3];
    const float* W2    = (const float*)d_in[4];
    const float* b2    = (const float*)d_in[5];
    const float* Wn    = (const float*)d_in[6];
    const float* bn    = (const float*)d_in[7];
    const float* Wl    = (const float*)d_in[8];
    const float* bl    = (const float*)d_in[9];
    const float* Woff  = (const float*)d_in[10];
    const float* boff  = (const float*)d_in[11];
    const float* Ww    = (const float*)d_in[12];
    const float* bw    = (const float*)d_in[13];
    const float* gamma = (const float*)d_in[14];
    const float* beta  = (const float*)d_in[15];
    float* out = (float*)d_out;

    int write_next = (out_size >= FEAT_OUT_ELEMS + NROWS) ? 1 : 0;

    static int smem_set = 0;
    if (!smem_set){
        cudaFuncSetAttribute(mlp_kernel, cudaFuncAttributeMaxDynamicSharedMemorySize,
                             MLP_SMEM_BYTES);
        smem_set = 1;
    }

    glob_kernel<<<256, 256>>>(feats);
    fill_kernel<<<2048, 256>>>(beta, (float4*)out);
    mlp_kernel<<<64, 512, MLP_SMEM_BYTES>>>(feats, pos, W1, b1, W2, b2, Wn, bn, Wl, bl,
                                            Woff, boff, Ww, bw, out, write_next);
    sample_ln_kernel<<<256, 512>>>(feats, gamma, beta, out);
}

// round 5
// speedup vs baseline: 1.1651x; 1.1651x over previous
#include <cuda_runtime.h>
#include <math.h>

#define C_    256
#define T_    8
#define H_    32
#define W_    32
#define L_    4
#define THW_  8192
#define NROWS 256              // L * 64 sample points
#define FEAT_OUT_ELEMS (C_*THW_*L_)   // 2097152
#define KC 128

// ---- scratch (device globals; no allocation) ----
__device__ float g_glob[L_*C_];           // glob[l][c]
__device__ float g_X [NROWS*768];         // MLP input rows
__device__ float g_H1[NROWS*256];
__device__ float g_H2[NROWS*256];
__device__ int   g_uq[NROWS*40];          // dedup indices (compact)
__device__ float g_uw[NROWS*40];          // dedup weights (compact)
__device__ int   g_nq[NROWS];             // dedup counts

__constant__ int c_tt[4] = {1,3,4,6};
__constant__ int c_hh[4] = {4,12,19,27};

__device__ __forceinline__ int flat_idx(int n){
    int it = n >> 4, ih = (n >> 2) & 3, iw = n & 3;
    return (c_tt[it]*H_ + c_hh[ih])*W_ + c_hh[iw];
}
__device__ __forceinline__ float sigmoidf_(float x){ return 1.0f/(1.0f+expf(-x)); }
__device__ __forceinline__ float invsigf_(float x){
    return logf(fmaxf(x,1e-5f)/fmaxf(1.0f-x,1e-5f));
}
__device__ __forceinline__ void cp_async16(void* smem_dst, const void* gmem_src){
    unsigned s = (unsigned)__cvta_generic_to_shared(smem_dst);
    asm volatile("cp.async.cg.shared.global [%0], [%1], 16;\n" :: "r"(s), "l"(gmem_src));
}
__device__ __forceinline__ void cp_commit(){ asm volatile("cp.async.commit_group;\n"); }
__device__ __forceinline__ void cp_wait0(){ asm volatile("cp.async.wait_group 0;\n"); }
__device__ __forceinline__ void cp_wait1(){ asm volatile("cp.async.wait_group 1;\n"); }

typedef unsigned long long ull;
__device__ __forceinline__ ull fma2_(ull a, ull b, ull c){
    ull d; asm("fma.rn.f32x2 %0, %1, %2, %3;" : "=l"(d) : "l"(a), "l"(b), "l"(c)); return d;
}
__device__ __forceinline__ ull pack2_(float x, float y){
    ull r; asm("mov.b64 %0, {%1, %2};" : "=l"(r) : "f"(x), "f"(y)); return r;
}
__device__ __forceinline__ float2 unpack2_(ull v){
    float2 r; asm("mov.b64 {%0, %1}, %2;" : "=f"(r.x), "=f"(r.y) : "l"(v)); return r;
}

// ============================================================
// Kernel 1: glob (channel mean) + beta fill, one block per channel
// ============================================================
__global__ void glob_fill_kernel(const float* __restrict__ feats,
                                 const float* __restrict__ beta,
                                 float4* __restrict__ out4){
    int c = blockIdx.x;
    int t = threadIdx.x;
    const float4* f4 = reinterpret_cast<const float4*>(feats + (size_t)c * (THW_*L_));
    float4 s = make_float4(0.f,0.f,0.f,0.f);
    for (int i = t; i < THW_; i += 256){
        float4 v = f4[i];
        s.x += v.x; s.y += v.y; s.z += v.z; s.w += v.w;
    }
    // beta fill of this channel's whole region (sample overwrites its spots later)
    float b = __ldg(&beta[c]);
    float4 bv = make_float4(b,b,b,b);
    float4* ob = out4 + (size_t)c * THW_;
    for (int i = t; i < THW_; i += 256) ob[i] = bv;

    __shared__ float4 sm[256];
    sm[t] = s;
    __syncthreads();
    for (int o = 128; o > 0; o >>= 1){
        if (t < o){
            float4 a = sm[t], bb = sm[t+o];
            sm[t] = make_float4(a.x+bb.x, a.y+bb.y, a.z+bb.z, a.w+bb.w);
        }
        __syncthreads();
    }
    if (t == 0){
        float4 v = sm[0];
        const float inv = 1.0f/8192.0f;
        g_glob[0*C_+c] = v.x*inv;
        g_glob[1*C_+c] = v.y*inv;
        g_glob[2*C_+c] = v.z*inv;
        g_glob[3*C_+c] = v.w*inv;
    }
}

// ============================================================
// Kernel 2: materialize X[256][768] = [feat | pos | glob]
// ============================================================
__global__ void xprep_kernel(const float* __restrict__ feats, const float* __restrict__ pos){
    int rr = blockIdx.x;
    int l  = rr >> 6;
    int p  = flat_idx(rr & 63);
    for (int k = threadIdx.x; k < 768; k += 256){
        float v;
        if (k < 256)       v = feats[((size_t)k*THW_ + p)*L_ + l];
        else if (k < 512)  v = pos  [((size_t)(k-256)*THW_ + p)*L_ + l];
        else               v = g_glob[l*C_ + (k-512)];
        g_X[rr*768 + k] = v;
    }
}

// ============================================================
// Tiled GEMM + relu: O[256,256] = relu(Xg[256,KDIM] @ Wg[KDIM,256] + bias)
// grid (8 col-tiles, 16 row-tiles), 256 threads.
// Tile: 16 rows x 32 cols; thread = (j = t&31, rp = t>>5) -> rows 2rp,2rp+1.
// smem: Xs[KDIM*18] (k-major, 16 rows padded to 18) + Wb[2][KC*32]
// ============================================================
template<int KDIM>
__device__ __forceinline__ void gemm_tile(const float* __restrict__ Xg,
                                          const float* __restrict__ Wg,
                                          const float* __restrict__ bias,
                                          float* __restrict__ Og){
    extern __shared__ float sm[];
    float* Xs  = sm;
    float* Wb0 = sm + KDIM*18;
    float* Wb1 = Wb0 + KC*32;

    int t  = threadIdx.x;
    int c0 = blockIdx.x * 32;
    int r0 = blockIdx.y * 16;
    constexpr int NCH = KDIM / KC;

    // prefetch W chunk 0
    {
        #pragma unroll
        for (int u = 0; u < 4; u++){
            int idx4 = t + u*256;                  // 1024 float4 = 128x32
            int kk = idx4 >> 3, j2 = (idx4 & 7)*4;
            cp_async16(Wb0 + idx4*4, Wg + (size_t)kk*256 + c0 + j2);
        }
        cp_commit();
    }

    // load Xs[k*18 + row] from Xg row-major (coalesced float4 reads)
    {
        const float4* X4 = reinterpret_cast<const float4*>(Xg);
        constexpr int K4 = KDIM/4;
        for (int idx4 = t; idx4 < 16*K4; idx4 += 256){
            int row = idx4 / K4;
            int k4  = idx4 - row*K4;
            float4 v = X4[(size_t)(r0+row)*K4 + k4];
            int k = k4*4;
            Xs[(k+0)*18 + row] = v.x;
            Xs[(k+1)*18 + row] = v.y;
            Xs[(k+2)*18 + row] = v.z;
            Xs[(k+3)*18 + row] = v.w;
        }
    }

    int j = t & 31, rp = t >> 5;
    ull accA = 0ULL, accB = 0ULL;

    #pragma unroll 1
    for (int ch = 0; ch < NCH; ch++){
        float* Wcur = (ch & 1) ? Wb1 : Wb0;
        float* Wnxt = (ch & 1) ? Wb0 : Wb1;
        if (ch + 1 < NCH){
            #pragma unroll
            for (int u = 0; u < 4; u++){
                int idx4 = t + u*256;
                int kk = idx4 >> 3, j2 = (idx4 & 7)*4;
                cp_async16(Wnxt + idx4*4, Wg + (size_t)((ch+1)*KC + kk)*256 + c0 + j2);
            }
            cp_commit();
            cp_wait1();
        } else {
            cp_wait0();
        }
        __syncthreads();
        const float* Xb = Xs + ch*KC*18 + 2*rp;
        #pragma unroll 8
        for (int kk = 0; kk < KC; kk += 2){
            float wA = Wcur[kk*32 + j];
            ull xA = *(const ull*)(Xb + kk*18);
            accA = fma2_(xA, pack2_(wA, wA), accA);
            float wB = Wcur[(kk+1)*32 + j];
            ull xB = *(const ull*)(Xb + (kk+1)*18);
            accB = fma2_(xB, pack2_(wB, wB), accB);
        }
        __syncthreads();
    }

    float2 a = unpack2_(accA), b2v = unpack2_(accB);
    float bb = __ldg(&bias[c0 + j]);
    int row = r0 + 2*rp;
    Og[(size_t)row*256 + c0 + j]     = fmaxf(a.x + b2v.x + bb, 0.f);
    Og[(size_t)(row+1)*256 + c0 + j] = fmaxf(a.y + b2v.y + bb, 0.f);
}

__global__ void __launch_bounds__(256, 2)
mlp1_kernel(const float* __restrict__ W1, const float* __restrict__ b1){
    gemm_tile<768>(g_X, W1, b1, g_H1);
}
__global__ void __launch_bounds__(256, 2)
mlp2_kernel(const float* __restrict__ W2, const float* __restrict__ b2){
    gemm_tile<256>(g_H1, W2, b2, g_H2);
}

// ============================================================
// Kernel 5: heads + dedup tables. 256 blocks (one row) x 128 threads.
// (wl head removed: softmax row-sum == 1 and LN is scale-invariant)
// ============================================================
__global__ void heads_kernel(
    const float* __restrict__ Wn, const float* __restrict__ bn,
    const float* __restrict__ Woff, const float* __restrict__ boff,
    const float* __restrict__ Ww, const float* __restrict__ bw,
    float* __restrict__ out, int write_next)
{
    __shared__ float Hs[256];
    __shared__ float HWn[768], HWo[192], HWw[128];
    __shared__ float HD[28];
    __shared__ float SPx[4], SPy[4], SPz[4], SPw[4];
    __shared__ int   cq[40];
    __shared__ float cw[40];
    __shared__ int   s_nq;

    int rr = blockIdx.x;
    int t  = threadIdx.x;
    int p  = flat_idx(rr & 63);

    Hs[t] = g_H2[rr*256 + t];
    Hs[t+128] = g_H2[rr*256 + t + 128];
    for (int k = t; k < 768; k += 128) HWn[k] = Wn[k];
    for (int k = t; k < 192; k += 128) HWo[k] = Woff[k];
    HWw[t] = Ww[t];
    __syncthreads();

    if (t < 3){                               // nxt
        float s = bn[t];
        #pragma unroll 8
        for (int k = 0; k < 256; k++) s = fmaf(Hs[k], HWn[k*3 + t], s);
        HD[t] = s;
    } else if (t >= 8 && t < 20){             // offsets
        int u = t - 8;
        int no = u / 3, jo = u - no*3;
        float s = boff[jo];
        #pragma unroll 8
        for (int dd = 0; dd < 64; dd++) s = fmaf(Hs[no*64+dd], HWo[dd*3 + jo], s);
        HD[8+u] = s;
    } else if (t >= 20 && t < 28){            // w_o logits
        int u = t - 20;
        int no = u >> 1, comp = u & 1;
        float s = bw[comp];
        #pragma unroll 8
        for (int dd = 0; dd < 64; dd++) s = fmaf(Hs[no*64+dd], HWw[dd*2 + comp], s);
        HD[20+u] = s;
    }
    __syncthreads();

    if (t == 0){
        int tq = p >> 10, hq = (p >> 5) & 31, wq = p & 31;
        float tn = (float)tq * (1.0f/7.0f);
        float hn = (float)hq * (1.0f/31.0f);
        float wn = (float)wq * (1.0f/31.0f);
        float ivt = invsigf_(tn), ivh = invsigf_(hn), ivw = invsigf_(wn);

        #pragma unroll
        for (int no = 0; no < 4; no++){
            float o0 = HD[8+no*3+0], o1 = HD[8+no*3+1], o2 = HD[8+no*3+2];
            float st = sigmoidf_(ivt + o0)*2.0f - 1.0f;
            float sh = sigmoidf_(ivh + o1)*2.0f - 1.0f;
            float sw = sigmoidf_(ivw + o2)*2.0f - 1.0f;
            SPx[no] = ((st + 1.0f)*32.0f - 1.0f)*0.5f;
            SPy[no] = ((sh + 1.0f)*32.0f - 1.0f)*0.5f;
            SPz[no] = ((sw + 1.0f)*8.0f  - 1.0f)*0.5f;
            float za = HD[20+no*2], zb = HD[21+no*2];
            SPw[no] = 1.0f/(1.0f + expf(za - zb));
        }

        if (write_next){
            float d0 = sigmoidf_(ivt + HD[0]) * 7.0f;
            float d1 = sigmoidf_(ivh + HD[1]) * 31.0f;
            float d2 = sigmoidf_(ivw + HD[2]) * 31.0f;
            int ni = 1024*(int)rintf(d0) + 32*(int)rintf(d1) + (int)rintf(d2);
            out[FEAT_OUT_ELEMS + rr] = (float)ni;
        }
    }
    __syncthreads();

    // ---- corner dedup (warp 0)
    if (t < 32){
        const unsigned full = 0xffffffffu;
        int lane = t;
        int no = lane >> 3, j = lane & 7;
        float ix = SPx[no], iy = SPy[no], iz = SPz[no];
        float wo = SPw[no];
        float x0f = floorf(ix), y0f = floorf(iy), z0f = floorf(iz);
        int dx = j & 1, dy = (j >> 1) & 1, dz = j >> 2;
        int xi = (int)x0f + dx, yi = (int)y0f + dy, zi = (int)z0f + dz;
        float fx = ix - x0f, fy = iy - y0f, fz = iz - z0f;
        float w = (dx ? fx : 1.0f-fx) * (dy ? fy : 1.0f-fy) * (dz ? fz : 1.0f-fz) * wo;
        bool valid = (xi >= 0) & (xi < W_) & (yi >= 0) & (yi < H_) & (zi >= 0) & (zi < T_);
        if (!valid) w = 0.0f;
        int q = (min(max(zi,0),T_-1)*H_ + min(max(yi,0),H_-1))*W_ + min(max(xi,0),W_-1);

        unsigned mask = __match_any_sync(full, q);
        float wsum = 0.0f;
        #pragma unroll
        for (int s2 = 0; s2 < 32; s2++){
            float wv = __shfl_sync(full, w, s2);
            int   qv = __shfl_sync(full, q, s2);
            if (qv == q) wsum += wv;
        }
        int leader = __ffs(mask) - 1;
        bool is_leader = (lane == leader);
        unsigned bal = __ballot_sync(full, is_leader);
        int pos = __popc(bal & ((1u << lane) - 1u));
        if (is_leader){ cq[pos] = q; cw[pos] = wsum; }
        __syncwarp();
        if (lane == 0){
            int nq = __popc(bal);
            bool found = false;
            for (int j2 = 0; j2 < nq; j2++){
                if (cq[j2] == p){ cw[j2] += 1.0f; found = true; break; }
            }
            if (!found){ cq[nq] = p; cw[nq] = 1.0f; nq++; }
            s_nq = nq;
            g_nq[rr] = nq;
        }
        __syncwarp();
        int nq = s_nq;
        if (lane < nq){
            g_uq[rr*40 + lane] = cq[lane];
            g_uw[rr*40 + lane] = cw[lane];
        }
        if (lane == 33-33){} // no-op
    }
}

// ============================================================
// Kernel 6: table-driven gather + LN, 256 blocks x 512 threads
// ============================================================
__global__ void __launch_bounds__(512, 2)
sample_ln_kernel(const float* __restrict__ feats,
                 const float* __restrict__ gamma,
                 const float* __restrict__ beta,
                 float* __restrict__ out)
{
    int b  = blockIdx.x;           // row = l*64 + n
    int l  = b >> 6;
    int p  = flat_idx(b & 63);
    int tid = threadIdx.x;

    __shared__ int    uq[40];
    __shared__ float  uw[40];
    __shared__ float  partial[256];
    __shared__ float2 sred[16];
    __shared__ int    s_nq;
    __shared__ float  s_mu, s_rstd;

    if (tid == 0) s_nq = g_nq[b];
    __syncthreads();
    int nq = s_nq;
    if (tid < nq){ uq[tid] = g_uq[b*40 + tid]; uw[tid] = g_uw[b*40 + tid]; }
    __syncthreads();

    int col  = tid & 255;
    int half = tid >> 8;
    const float* fb = feats + (size_t)col*(THW_*L_) + l;

    float acc = 0.0f;
    for (int j = half; j < nq; j += 2)
        acc = fmaf(uw[j], __ldg(fb + (size_t)uq[j]*L_), acc);

    if (half) partial[col] = acc;
    __syncthreads();

    float v = 0.0f;
    if (!half) v = acc + partial[col];

    const unsigned full = 0xffffffffu;
    float sx = v, sy = v*v;
    #pragma unroll
    for (int o = 16; o > 0; o >>= 1){
        sx += __shfl_xor_sync(full, sx, o);
        sy += __shfl_xor_sync(full, sy, o);
    }
    int lane = tid & 31, wrp = tid >> 5;
    if (lane == 0) sred[wrp] = make_float2(sx, sy);
    __syncthreads();
    if (tid < 16){
        float2 a = sred[tid];
        #pragma unroll
        for (int o = 8; o > 0; o >>= 1){
            a.x += __shfl_xor_sync(0xffffu, a.x, o);
            a.y += __shfl_xor_sync(0xffffu, a.y, o);
        }
        if (tid == 0){
            float mu  = a.x * (1.0f/256.0f);
            float var = a.y * (1.0f/256.0f) - mu*mu;
            s_mu = mu;
            s_rstd = rsqrtf(var + 1e-5f);
        }
    }
    __syncthreads();

    if (!half){
        float o = (v - s_mu) * s_rstd * gamma[col] + beta[col];
        out[((size_t)col*THW_ + p)*L_ + l] = o;
    }
}

// ============================================================
extern "C" void kernel_launch(void* const* d_in, const int* in_sizes, int n_in,
                              void* d_out, int out_size)
{
    const float* feats = (const float*)d_in[0];
    const float* pos   = (const float*)d_in[1];
    const float* W1    = (const float*)d_in[2];
    const float* b1    = (const float*)d_in[3];
    const float* W2    = (const float*)d_in[4];
    const float* b2    = (const float*)d_in[5];
    const float* Wn    = (const float*)d_in[6];
    const float* bn    = (const float*)d_in[7];
    // d_in[8] = Wl, d_in[9] = bl  (dead: softmax row-sum == 1, LN scale-invariant)
    const float* Woff  = (const float*)d_in[10];
    const float* boff  = (const float*)d_in[11];
    const float* Ww    = (const float*)d_in[12];
    const float* bw    = (const float*)d_in[13];
    const float* gamma = (const float*)d_in[14];
    const float* beta  = (const float*)d_in[15];
    float* out = (float*)d_out;

    int write_next = (out_size >= FEAT_OUT_ELEMS + NROWS) ? 1 : 0;

    const int SM1 = (768*18 + 2*KC*32) * 4;   // 88064 B
    const int SM2 = (256*18 + 2*KC*32) * 4;   // 51200 B

    static int smem_set = 0;
    if (!smem_set){
        cudaFuncSetAttribute(mlp1_kernel, cudaFuncAttributeMaxDynamicSharedMemorySize, SM1);
        cudaFuncSetAttribute(mlp2_kernel, cudaFuncAttributeMaxDynamicSharedMemorySize, SM2);
        smem_set = 1;
    }

    glob_fill_kernel<<<256, 256>>>(feats, beta, (float4*)out);
    xprep_kernel<<<256, 256>>>(feats, pos);
    mlp1_kernel<<<dim3(8,16), 256, SM1>>>(W1, b1);
    mlp2_kernel<<<dim3(8,16), 256, SM2>>>(W2, b2);
    heads_kernel<<<256, 128>>>(Wn, bn, Woff, boff, Ww, bw, out, write_next);
    sample_ln_kernel<<<256, 512>>>(feats, gamma, beta, out);
}

// round 6
// speedup vs baseline: 1.1658x; 1.0006x over previous
#include <cuda_runtime.h>
#include <math.h>

#define C_    256
#define T_    8
#define H_    32
#define W_    32
#define L_    4
#define THW_  8192
#define NROWS 256              // L * 64 sample points
#define FEAT_OUT_ELEMS (C_*THW_*L_)   // 2097152
#define KC 128

// ---- scratch (device globals; no allocation) ----
__device__ float g_glob[L_*C_];           // glob[l][c]
__device__ float g_X [NROWS*768];         // MLP input rows
__device__ float g_H1[NROWS*256];
__device__ float g_H2[NROWS*256];
__device__ int   g_uq[NROWS*40];          // dedup indices (compact)
__device__ float g_uw[NROWS*40];          // dedup weights (compact)
__device__ int   g_nq[NROWS];             // dedup counts

__constant__ int c_tt[4] = {1,3,4,6};
__constant__ int c_hh[4] = {4,12,19,27};

__device__ __forceinline__ int flat_idx(int n){
    int it = n >> 4, ih = (n >> 2) & 3, iw = n & 3;
    return (c_tt[it]*H_ + c_hh[ih])*W_ + c_hh[iw];
}
__device__ __forceinline__ float sigmoidf_(float x){ return 1.0f/(1.0f+expf(-x)); }
__device__ __forceinline__ float invsigf_(float x){
    return logf(fmaxf(x,1e-5f)/fmaxf(1.0f-x,1e-5f));
}
__device__ __forceinline__ void cp_async16(void* smem_dst, const void* gmem_src){
    unsigned s = (unsigned)__cvta_generic_to_shared(smem_dst);
    asm volatile("cp.async.cg.shared.global [%0], [%1], 16;\n" :: "r"(s), "l"(gmem_src));
}
__device__ __forceinline__ void cp_commit(){ asm volatile("cp.async.commit_group;\n"); }
__device__ __forceinline__ void cp_wait0(){ asm volatile("cp.async.wait_group 0;\n"); }
__device__ __forceinline__ void cp_wait1(){ asm volatile("cp.async.wait_group 1;\n"); }

typedef unsigned long long ull;
__device__ __forceinline__ ull fma2_(ull a, ull b, ull c){
    ull d; asm("fma.rn.f32x2 %0, %1, %2, %3;" : "=l"(d) : "l"(a), "l"(b), "l"(c)); return d;
}
__device__ __forceinline__ ull pack2_(float x, float y){
    ull r; asm("mov.b64 %0, {%1, %2};" : "=l"(r) : "f"(x), "f"(y)); return r;
}
__device__ __forceinline__ float2 unpack2_(ull v){
    float2 r; asm("mov.b64 {%0, %1}, %2;" : "=f"(r.x), "=f"(r.y) : "l"(v)); return r;
}

// ============================================================
// Kernel 1: glob (channel mean) + beta fill, one block per channel
// ============================================================
__global__ void glob_fill_kernel(const float* __restrict__ feats,
                                 const float* __restrict__ beta,
                                 float4* __restrict__ out4){
    int c = blockIdx.x;
    int t = threadIdx.x;
    const float4* f4 = reinterpret_cast<const float4*>(feats + (size_t)c * (THW_*L_));
    float4 s = make_float4(0.f,0.f,0.f,0.f);
    for (int i = t; i < THW_; i += 256){
        float4 v = f4[i];
        s.x += v.x; s.y += v.y; s.z += v.z; s.w += v.w;
    }
    // beta fill of this channel's whole region (sample overwrites its spots later)
    float b = __ldg(&beta[c]);
    float4 bv = make_float4(b,b,b,b);
    float4* ob = out4 + (size_t)c * THW_;
    for (int i = t; i < THW_; i += 256) ob[i] = bv;

    __shared__ float4 sm[256];
    sm[t] = s;
    __syncthreads();
    for (int o = 128; o > 0; o >>= 1){
        if (t < o){
            float4 a = sm[t], bb = sm[t+o];
            sm[t] = make_float4(a.x+bb.x, a.y+bb.y, a.z+bb.z, a.w+bb.w);
        }
        __syncthreads();
    }
    if (t == 0){
        float4 v = sm[0];
        const float inv = 1.0f/8192.0f;
        g_glob[0*C_+c] = v.x*inv;
        g_glob[1*C_+c] = v.y*inv;
        g_glob[2*C_+c] = v.z*inv;
        g_glob[3*C_+c] = v.w*inv;
    }
}

// ============================================================
// Kernel 2: materialize X[256][768] = [feat | pos | glob]
// ============================================================
__global__ void xprep_kernel(const float* __restrict__ feats, const float* __restrict__ pos){
    int rr = blockIdx.x;
    int l  = rr >> 6;
    int p  = flat_idx(rr & 63);
    for (int k = threadIdx.x; k < 768; k += 256){
        float v;
        if (k < 256)       v = feats[((size_t)k*THW_ + p)*L_ + l];
        else if (k < 512)  v = pos  [((size_t)(k-256)*THW_ + p)*L_ + l];
        else               v = g_glob[l*C_ + (k-512)];
        g_X[rr*768 + k] = v;
    }
}

// ============================================================
// Tiled GEMM + relu: O[256,256] = relu(Xg[256,KDIM] @ Wg[KDIM,256] + bias)
// grid (8 col-tiles, 16 row-tiles), 256 threads.
// Tile: 16 rows x 32 cols; thread = (j = t&31, rp = t>>5) -> rows 2rp,2rp+1.
// smem: Xs[KDIM*18] (k-major, 16 rows padded to 18) + Wb[2][KC*32]
// ============================================================
template<int KDIM>
__device__ __forceinline__ void gemm_tile(const float* __restrict__ Xg,
                                          const float* __restrict__ Wg,
                                          const float* __restrict__ bias,
                                          float* __restrict__ Og){
    extern __shared__ float sm[];
    float* Xs  = sm;
    float* Wb0 = sm + KDIM*18;
    float* Wb1 = Wb0 + KC*32;

    int t  = threadIdx.x;
    int c0 = blockIdx.x * 32;
    int r0 = blockIdx.y * 16;
    constexpr int NCH = KDIM / KC;

    // prefetch W chunk 0
    {
        #pragma unroll
        for (int u = 0; u < 4; u++){
            int idx4 = t + u*256;                  // 1024 float4 = 128x32
            int kk = idx4 >> 3, j2 = (idx4 & 7)*4;
            cp_async16(Wb0 + idx4*4, Wg + (size_t)kk*256 + c0 + j2);
        }
        cp_commit();
    }

    // load Xs[k*18 + row] from Xg row-major (coalesced float4 reads)
    {
        const float4* X4 = reinterpret_cast<const float4*>(Xg);
        constexpr int K4 = KDIM/4;
        for (int idx4 = t; idx4 < 16*K4; idx4 += 256){
            int row = idx4 / K4;
            int k4  = idx4 - row*K4;
            float4 v = X4[(size_t)(r0+row)*K4 + k4];
            int k = k4*4;
            Xs[(k+0)*18 + row] = v.x;
            Xs[(k+1)*18 + row] = v.y;
            Xs[(k+2)*18 + row] = v.z;
            Xs[(k+3)*18 + row] = v.w;
        }
    }

    int j = t & 31, rp = t >> 5;
    ull accA = 0ULL, accB = 0ULL;

    #pragma unroll 1
    for (int ch = 0; ch < NCH; ch++){
        float* Wcur = (ch & 1) ? Wb1 : Wb0;
        float* Wnxt = (ch & 1) ? Wb0 : Wb1;
        if (ch + 1 < NCH){
            #pragma unroll
            for (int u = 0; u < 4; u++){
                int idx4 = t + u*256;
                int kk = idx4 >> 3, j2 = (idx4 & 7)*4;
                cp_async16(Wnxt + idx4*4, Wg + (size_t)((ch+1)*KC + kk)*256 + c0 + j2);
            }
            cp_commit();
            cp_wait1();
        } else {
            cp_wait0();
        }
        __syncthreads();
        const float* Xb = Xs + ch*KC*18 + 2*rp;
        #pragma unroll 8
        for (int kk = 0; kk < KC; kk += 2){
            float wA = Wcur[kk*32 + j];
            ull xA = *(const ull*)(Xb + kk*18);
            accA = fma2_(xA, pack2_(wA, wA), accA);
            float wB = Wcur[(kk+1)*32 + j];
            ull xB = *(const ull*)(Xb + (kk+1)*18);
            accB = fma2_(xB, pack2_(wB, wB), accB);
        }
        __syncthreads();
    }

    float2 a = unpack2_(accA), b2v = unpack2_(accB);
    float bb = __ldg(&bias[c0 + j]);
    int row = r0 + 2*rp;
    Og[(size_t)row*256 + c0 + j]     = fmaxf(a.x + b2v.x + bb, 0.f);
    Og[(size_t)(row+1)*256 + c0 + j] = fmaxf(a.y + b2v.y + bb, 0.f);
}

__global__ void __launch_bounds__(256, 2)
mlp1_kernel(const float* __restrict__ W1, const float* __restrict__ b1){
    gemm_tile<768>(g_X, W1, b1, g_H1);
}
__global__ void __launch_bounds__(256, 2)
mlp2_kernel(const float* __restrict__ W2, const float* __restrict__ b2){
    gemm_tile<256>(g_H1, W2, b2, g_H2);
}

// ============================================================
// Kernel 5: heads + dedup tables. 256 blocks (one row) x 128 threads.
// (wl head removed: softmax row-sum == 1 and LN is scale-invariant)
// ============================================================
__global__ void heads_kernel(
    const float* __restrict__ Wn, const float* __restrict__ bn,
    const float* __restrict__ Woff, const float* __restrict__ boff,
    const float* __restrict__ Ww, const float* __restrict__ bw,
    float* __restrict__ out, int write_next)
{
    __shared__ float Hs[256];
    __shared__ float HWn[768], HWo[192], HWw[128];
    __shared__ float HD[28];
    __shared__ float SPx[4], SPy[4], SPz[4], SPw[4];
    __shared__ int   cq[40];
    __shared__ float cw[40];
    __shared__ int   s_nq;

    int rr = blockIdx.x;
    int t  = threadIdx.x;
    int p  = flat_idx(rr & 63);

    Hs[t] = g_H2[rr*256 + t];
    Hs[t+128] = g_H2[rr*256 + t + 128];
    for (int k = t; k < 768; k += 128) HWn[k] = Wn[k];
    for (int k = t; k < 192; k += 128) HWo[k] = Woff[k];
    HWw[t] = Ww[t];
    __syncthreads();

    if (t < 3){                               // nxt
        float s = bn[t];
        #pragma unroll 8
        for (int k = 0; k < 256; k++) s = fmaf(Hs[k], HWn[k*3 + t], s);
        HD[t] = s;
    } else if (t >= 8 && t < 20){             // offsets
        int u = t - 8;
        int no = u / 3, jo = u - no*3;
        float s = boff[jo];
        #pragma unroll 8
        for (int dd = 0; dd < 64; dd++) s = fmaf(Hs[no*64+dd], HWo[dd*3 + jo], s);
        HD[8+u] = s;
    } else if (t >= 20 && t < 28){            // w_o logits
        int u = t - 20;
        int no = u >> 1, comp = u & 1;
        float s = bw[comp];
        #pragma unroll 8
        for (int dd = 0; dd < 64; dd++) s = fmaf(Hs[no*64+dd], HWw[dd*2 + comp], s);
        HD[20+u] = s;
    }
    __syncthreads();

    if (t == 0){
        int tq = p >> 10, hq = (p >> 5) & 31, wq = p & 31;
        float tn = (float)tq * (1.0f/7.0f);
        float hn = (float)hq * (1.0f/31.0f);
        float wn = (float)wq * (1.0f/31.0f);
        float ivt = invsigf_(tn), ivh = invsigf_(hn), ivw = invsigf_(wn);

        #pragma unroll
        for (int no = 0; no < 4; no++){
            float o0 = HD[8+no*3+0], o1 = HD[8+no*3+1], o2 = HD[8+no*3+2];
            float st = sigmoidf_(ivt + o0)*2.0f - 1.0f;
            float sh = sigmoidf_(ivh + o1)*2.0f - 1.0f;
            float sw = sigmoidf_(ivw + o2)*2.0f - 1.0f;
            SPx[no] = ((st + 1.0f)*32.0f - 1.0f)*0.5f;
            SPy[no] = ((sh + 1.0f)*32.0f - 1.0f)*0.5f;
            SPz[no] = ((sw + 1.0f)*8.0f  - 1.0f)*0.5f;
            float za = HD[20+no*2], zb = HD[21+no*2];
            SPw[no] = 1.0f/(1.0f + expf(za - zb));
        }

        if (write_next){
            float d0 = sigmoidf_(ivt + HD[0]) * 7.0f;
            float d1 = sigmoidf_(ivh + HD[1]) * 31.0f;
            float d2 = sigmoidf_(ivw + HD[2]) * 31.0f;
            int ni = 1024*(int)rintf(d0) + 32*(int)rintf(d1) + (int)rintf(d2);
            out[FEAT_OUT_ELEMS + rr] = (float)ni;
        }
    }
    __syncthreads();

    // ---- corner dedup (warp 0)
    if (t < 32){
        const unsigned full = 0xffffffffu;
        int lane = t;
        int no = lane >> 3, j = lane & 7;
        float ix = SPx[no], iy = SPy[no], iz = SPz[no];
        float wo = SPw[no];
        float x0f = floorf(ix), y0f = floorf(iy), z0f = floorf(iz);
        int dx = j & 1, dy = (j >> 1) & 1, dz = j >> 2;
        int xi = (int)x0f + dx, yi = (int)y0f + dy, zi = (int)z0f + dz;
        float fx = ix - x0f, fy = iy - y0f, fz = iz - z0f;
        float w = (dx ? fx : 1.0f-fx) * (dy ? fy : 1.0f-fy) * (dz ? fz : 1.0f-fz) * wo;
        bool valid = (xi >= 0) & (xi < W_) & (yi >= 0) & (yi < H_) & (zi >= 0) & (zi < T_);
        if (!valid) w = 0.0f;
        int q = (min(max(zi,0),T_-1)*H_ + min(max(yi,0),H_-1))*W_ + min(max(xi,0),W_-1);

        unsigned mask = __match_any_sync(full, q);
        float wsum = 0.0f;
        #pragma unroll
        for (int s2 = 0; s2 < 32; s2++){
            float wv = __shfl_sync(full, w, s2);
            int   qv = __shfl_sync(full, q, s2);
            if (qv == q) wsum += wv;
        }
        int leader = __ffs(mask) - 1;
        bool is_leader = (lane == leader);
        unsigned bal = __ballot_sync(full, is_leader);
        int pos = __popc(bal & ((1u << lane) - 1u));
        if (is_leader){ cq[pos] = q; cw[pos] = wsum; }
        __syncwarp();
        if (lane == 0){
            int nq = __popc(bal);
            bool found = false;
            for (int j2 = 0; j2 < nq; j2++){
                if (cq[j2] == p){ cw[j2] += 1.0f; found = true; break; }
            }
            if (!found){ cq[nq] = p; cw[nq] = 1.0f; nq++; }
            s_nq = nq;
            g_nq[rr] = nq;
        }
        __syncwarp();
        int nq = s_nq;
        if (lane < nq){
            g_uq[rr*40 + lane] = cq[lane];
            g_uw[rr*40 + lane] = cw[lane];
        }
        if (lane == 33-33){} // no-op
    }
}

// ============================================================
// Kernel 6: table-driven gather + LN, 256 blocks x 512 threads
// ============================================================
__global__ void __launch_bounds__(512, 2)
sample_ln_kernel(const float* __restrict__ feats,
                 const float* __restrict__ gamma,
                 const float* __restrict__ beta,
                 float* __restrict__ out)
{
    int b  = blockIdx.x;           // row = l*64 + n
    int l  = b >> 6;
    int p  = flat_idx(b & 63);
    int tid = threadIdx.x;

    __shared__ int    uq[40];
    __shared__ float  uw[40];
    __shared__ float  partial[256];
    __shared__ float2 sred[16];
    __shared__ int    s_nq;
    __shared__ float  s_mu, s_rstd;

    if (tid == 0) s_nq = g_nq[b];
    __syncthreads();
    int nq = s_nq;
    if (tid < nq){ uq[tid] = g_uq[b*40 + tid]; uw[tid] = g_uw[b*40 + tid]; }
    __syncthreads();

    int col  = tid & 255;
    int half = tid >> 8;
    const float* fb = feats + (size_t)col*(THW_*L_) + l;

    float acc = 0.0f;
    for (int j = half; j < nq; j += 2)
        acc = fmaf(uw[j], __ldg(fb + (size_t)uq[j]*L_), acc);

    if (half) partial[col] = acc;
    __syncthreads();

    float v = 0.0f;
    if (!half) v = acc + partial[col];

    const unsigned full = 0xffffffffu;
    float sx = v, sy = v*v;
    #pragma unroll
    for (int o = 16; o > 0; o >>= 1){
        sx += __shfl_xor_sync(full, sx, o);
        sy += __shfl_xor_sync(full, sy, o);
    }
    int lane = tid & 31, wrp = tid >> 5;
    if (lane == 0) sred[wrp] = make_float2(sx, sy);
    __syncthreads();
    if (tid < 16){
        float2 a = sred[tid];
        #pragma unroll
        for (int o = 8; o > 0; o >>= 1){
            a.x += __shfl_xor_sync(0xffffu, a.x, o);
            a.y += __shfl_xor_sync(0xffffu, a.y, o);
        }
        if (tid == 0){
            float mu  = a.x * (1.0f/256.0f);
            float var = a.y * (1.0f/256.0f) - mu*mu;
            s_mu = mu;
            s_rstd = rsqrtf(var + 1e-5f);
        }
    }
    __syncthreads();

    if (!half){
        float o = (v - s_mu) * s_rstd * gamma[col] + beta[col];
        out[((size_t)col*THW_ + p)*L_ + l] = o;
    }
}

// ============================================================
extern "C" void kernel_launch(void* const* d_in, const int* in_sizes, int n_in,
                              void* d_out, int out_size)
{
    const float* feats = (const float*)d_in[0];
    const float* pos   = (const float*)d_in[1];
    const float* W1    = (const float*)d_in[2];
    const float* b1    = (const float*)d_in[3];
    const float* W2    = (const float*)d_in[4];
    const float* b2    = (const float*)d_in[5];
    const float* Wn    = (const float*)d_in[6];
    const float* bn    = (const float*)d_in[7];
    // d_in[8] = Wl, d_in[9] = bl  (dead: softmax row-sum == 1, LN scale-invariant)
    const float* Woff  = (const float*)d_in[10];
    const float* boff  = (const float*)d_in[11];
    const float* Ww    = (const float*)d_in[12];
    const float* bw    = (const float*)d_in[13];
    const float* gamma = (const float*)d_in[14];
    const float* beta  = (const float*)d_in[15];
    float* out = (float*)d_out;

    int write_next = (out_size >= FEAT_OUT_ELEMS + NROWS) ? 1 : 0;

    const int SM1 = (768*18 + 2*KC*32) * 4;   // 88064 B
    const int SM2 = (256*18 + 2*KC*32) * 4;   // 51200 B

    static int smem_set = 0;
    if (!smem_set){
        cudaFuncSetAttribute(mlp1_kernel, cudaFuncAttributeMaxDynamicSharedMemorySize, SM1);
        cudaFuncSetAttribute(mlp2_kernel, cudaFuncAttributeMaxDynamicSharedMemorySize, SM2);
        smem_set = 1;
    }

    glob_fill_kernel<<<256, 256>>>(feats, beta, (float4*)out);
    xprep_kernel<<<256, 256>>>(feats, pos);
    mlp1_kernel<<<dim3(8,16), 256, SM1>>>(W1, b1);
    mlp2_kernel<<<dim3(8,16), 256, SM2>>>(W2, b2);
    heads_kernel<<<256, 128>>>(Wn, bn, Woff, boff, Ww, bw, out, write_next);
    sample_ln_kernel<<<256, 512>>>(feats, gamma, beta, out);
}